// round 4
// baseline (speedup 1.0000x reference)
#include <cuda_runtime.h>
#include <math.h>

#define NMAX 22528
#define GMX 32
#define LCAP 2048
#define TOPK_K 15
#define BG_LAB 15
#define PI_F   3.14159265358979323846f
#define HPI_F  1.57079632679489661923f

// -------- persistent device scratch (zero after every launch) --------
__device__ int g_cnt[GMX];                    // static-init 0
__device__ unsigned long long g_anchorKey[GMX];
__device__ int g_ack;                         // static-init 0
__device__ float g_lv[GMX * LCAP];            // list values (cost)
__device__ int   g_li[GMX * LCAP];            // list point indices

// ---------------------------------------------------------------------------
// Rotated IoU (reference-faithful polygon construction)
// ---------------------------------------------------------------------------
__device__ __forceinline__ void make_corners(float cx, float cy, float w, float h,
                                             float c, float s, float* X, float* Y)
{
    float w2 = w * 0.5f, h2 = h * 0.5f;
    X[0] = cx + (w2 * c + h2 * s);  Y[0] = cy + (w2 * s - h2 * c);
    X[1] = cx + (w2 * c - h2 * s);  Y[1] = cy + (w2 * s + h2 * c);
    X[2] = cx + (-w2 * c - h2 * s); Y[2] = cy + (-w2 * s + h2 * c);
    X[3] = cx + (-w2 * c + h2 * s); Y[3] = cy + (-w2 * s - h2 * c);
}

__device__ float riou_pair(float b1cx, float b1cy, float b1w, float b1h,
                           float b1c, float b1s, float a1,
                           float b2cx, float b2cy, float b2w, float b2h,
                           float b2c, float b2s, float a2)
{
    {
        float ddx = b1cx - b2cx, ddy = b1cy - b2cy;
        float r1 = 0.5f * sqrtf(b1w * b1w + b1h * b1h);
        float r2 = 0.5f * sqrtf(b2w * b2w + b2h * b2h);
        float rrs = r1 + r2 + 0.5f;
        if (ddx * ddx + ddy * ddy > rrs * rrs) return 0.0f;
    }

    float c1x[4], c1y[4], c2x[4], c2y[4];
    make_corners(b1cx, b1cy, b1w, b1h, b1c, b1s, c1x, c1y);
    make_corners(b2cx, b2cy, b2w, b2h, b2c, b2s, c2x, c2y);

    float X[24], Y[24], A[24];
    int cnt = 0;
    float sx = 0.0f, sy = 0.0f;

#pragma unroll
    for (int a = 0; a < 4; a++) {
        float px = c1x[a], py = c1y[a];
        float d1x = c1x[(a + 1) & 3] - px, d1y = c1y[(a + 1) & 3] - py;
#pragma unroll
        for (int b = 0; b < 4; b++) {
            float qx = c2x[b], qy = c2y[b];
            float d2x = c2x[(b + 1) & 3] - qx, d2y = c2y[(b + 1) & 3] - qy;
            float den = d1x * d2y - d1y * d2x;
            bool dok = fabsf(den) > 1e-10f;
            float safe = dok ? den : 1.0f;
            float qpx = qx - px, qpy = qy - py;
            float t = (qpx * d2y - qpy * d2x) / safe;
            float u = (qpx * d1y - qpy * d1x) / safe;
            if (dok && t >= 0.0f && t <= 1.0f && u >= 0.0f && u <= 1.0f) {
                float ix = px + t * d1x, iy = py + t * d1y;
                X[cnt] = ix; Y[cnt] = iy; cnt++;
                sx += ix; sy += iy;
            }
        }
    }
#pragma unroll
    for (int a = 0; a < 4; a++) {
        float rx = c1x[a] - b2cx, ry = c1y[a] - b2cy;
        float xx = rx * b2c + ry * b2s;
        float yy = -rx * b2s + ry * b2c;
        if (fabsf(xx) <= b2w * 0.5f + 1e-6f && fabsf(yy) <= b2h * 0.5f + 1e-6f) {
            X[cnt] = c1x[a]; Y[cnt] = c1y[a]; cnt++;
            sx += c1x[a]; sy += c1y[a];
        }
    }
#pragma unroll
    for (int b = 0; b < 4; b++) {
        float rx = c2x[b] - b1cx, ry = c2y[b] - b1cy;
        float xx = rx * b1c + ry * b1s;
        float yy = -rx * b1s + ry * b1c;
        if (fabsf(xx) <= b1w * 0.5f + 1e-6f && fabsf(yy) <= b1h * 0.5f + 1e-6f) {
            X[cnt] = c2x[b]; Y[cnt] = c2y[b]; cnt++;
            sx += c2x[b]; sy += c2y[b];
        }
    }

    if (cnt == 0) return 0.0f;
    float ctrx = sx / (float)cnt, ctry = sy / (float)cnt;

    for (int j = 0; j < cnt; j++) A[j] = atan2f(Y[j] - ctry, X[j] - ctrx);
    for (int j = 1; j < cnt; j++) {
        float aj = A[j], xj = X[j], yj = Y[j];
        int k = j - 1;
        while (k >= 0 && A[k] > aj) {
            A[k + 1] = A[k]; X[k + 1] = X[k]; Y[k + 1] = Y[k]; k--;
        }
        A[k + 1] = aj; X[k + 1] = xj; Y[k + 1] = yj;
    }
    float acc = 0.0f;
    for (int j = 0; j < cnt; j++) {
        int k = (j + 1 < cnt) ? j + 1 : 0;
        float vax = X[j] - ctrx, vay = Y[j] - ctry;
        float vbx = X[k] - ctrx, vby = Y[k] - ctry;
        acc += vax * vby - vay * vbx;
    }
    float inter = 0.5f * fabsf(acc);
    return inter / fmaxf(a1 + a2 - inter, 1e-8f);
}

// ---------------------------------------------------------------------------
// Kernel 1: point-major gating + lazy decode/softmax/IoU + compaction + anchor
// ---------------------------------------------------------------------------
__global__ void __launch_bounds__(256)
kMain(const float* __restrict__ pts, const float* __restrict__ rr,
      const float* __restrict__ stride, const float* __restrict__ gtb,
      const int* __restrict__ glab, const float* __restrict__ preds,
      const float* __restrict__ probs, int N, int G)
{
    __shared__ float sg[GMX * 8];   // cx,cy,w,h,cos,sin,angle,area
    __shared__ int sl[GMX];
    __shared__ unsigned long long sA[GMX];
    int tid = threadIdx.x;
    if (tid < G) {
        float cx = gtb[tid * 5 + 0], cy = gtb[tid * 5 + 1];
        float w = gtb[tid * 5 + 2], h = gtb[tid * 5 + 3], a = gtb[tid * 5 + 4];
        sg[tid * 8 + 0] = cx; sg[tid * 8 + 1] = cy;
        sg[tid * 8 + 2] = w;  sg[tid * 8 + 3] = h;
        sg[tid * 8 + 4] = cosf(a); sg[tid * 8 + 5] = sinf(a);
        sg[tid * 8 + 6] = a; sg[tid * 8 + 7] = w * h;
        sl[tid] = glab[tid];
    }
    if (tid < GMX) sA[tid] = 0ULL;
    __syncthreads();

    int i = blockIdx.x * blockDim.x + tid;
    int lane = tid & 31;
    bool inb = (i < N);

    float px = 0.f, py = 0.f, st = 1.f, r0 = 0.f, r1 = 0.f;
    if (inb) {
        px = pts[i * 2 + 0]; py = pts[i * 2 + 1];
        st = stride[i];
        r0 = rr[i * 2 + 0]; r1 = rr[i * 2 + 1];
    }
    float crad = 1.5f * st;

    unsigned mask = 0u;
    for (int g = 0; g < G; ++g) {
        float bcx = sg[g * 8 + 0], bcy = sg[g * 8 + 1];
        float w = sg[g * 8 + 2], h = sg[g * 8 + 3];
        float c = sg[g * 8 + 4], s = sg[g * 8 + 5];
        float offx = px - bcx, offy = py - bcy;
        float ox = offx * c + offy * s;
        float oy = -offx * s + offy * c;
        float t0 = w * 0.5f + ox, t1 = h * 0.5f + oy;
        float t2 = w * 0.5f - ox, t3 = h * 0.5f - oy;
        float mn = fminf(fminf(t0, t1), fminf(t2, t3));
        float mx = fmaxf(fmaxf(t0, t1), fmaxf(t2, t3));
        float u = 2.0f * ox / w, v = 2.0f * oy / h;
        float cent = fmaxf(1.0f - sqrtf((u * u + v * v + 1e-8f) * 0.5f), 0.0f);
        bool valid = inb && (mn > 0.0f) && (fabsf(ox) < crad) && (fabsf(oy) < crad)
                     && (mx >= r0) && (mx <= r1);
        if (valid) mask |= 1u << g;

        // anchor key reduce (all points, incl. invalid): (cent desc, idx asc)
        unsigned long long akey = inb
            ? (((unsigned long long)__float_as_uint(cent) << 32) | (unsigned)(~(unsigned)i))
            : 0ULL;
#pragma unroll
        for (int off = 16; off > 0; off >>= 1) {
            unsigned long long o = __shfl_down_sync(0xFFFFFFFFu, akey, off);
            if (o > akey) akey = o;
        }
        if (lane == 0 && akey != 0ULL) atomicMax(&sA[g], akey);
    }
    __syncthreads();
    if (tid < G) {
        unsigned long long v = sA[tid];
        if (v != 0ULL) atomicMax(&g_anchorKey[tid], v);
    }

    // warp-union of valid gts
    unsigned wm = mask;
#pragma unroll
    for (int off = 16; off > 0; off >>= 1) wm |= __shfl_xor_sync(0xFFFFFFFFu, wm, off);
    if (wm == 0u) return;

    // lazy per-point decode + softmax prep (only threads with any valid gt)
    float bcx1 = 0.f, bcy1 = 0.f, bw1 = 0.f, bh1 = 0.f, bc1 = 1.f, bs1 = 0.f, ar1 = 0.f;
    float pm = 0.f, psum = 1.f;
    if (mask) {
        float d0 = preds[i * 5 + 0] * st, d1 = preds[i * 5 + 1] * st;
        float d2 = preds[i * 5 + 2] * st, d3 = preds[i * 5 + 3] * st;
        float ang = preds[i * 5 + 4];
        float c = cosf(ang), s = sinf(ang);
        bw1 = d0 + d2; bh1 = d1 + d3;
        float otx = (d2 - d0) * 0.5f, oty = (d3 - d1) * 0.5f;
        bcx1 = px + (c * otx - s * oty);
        bcy1 = py + (s * otx + c * oty);
        float x = ang + HPI_F;
        float r = fmodf(x, PI_F);
        if (r < 0.0f) r += PI_F;
        float a = r - HPI_F;
        bc1 = cosf(a); bs1 = sinf(a);
        ar1 = bw1 * bh1;

        pm = -1e30f;
#pragma unroll
        for (int k = 0; k < 15; k++) pm = fmaxf(pm, probs[i * 15 + k]);
        psum = 0.0f;
#pragma unroll
        for (int k = 0; k < 15; k++) psum += expf(probs[i * 15 + k] - pm);
    }

    while (wm) {
        int g = __ffs(wm) - 1;
        wm &= wm - 1u;
        bool v = (mask >> g) & 1u;
        float cost = 0.0f;
        if (v) {
            float bcx = sg[g * 8 + 0], bcy = sg[g * 8 + 1];
            float w = sg[g * 8 + 2], h = sg[g * 8 + 3];
            float c = sg[g * 8 + 4], s = sg[g * 8 + 5];
            float a2 = sg[g * 8 + 7];
            float offx = px - bcx, offy = py - bcy;
            float ox = offx * c + offy * s;
            float oy = -offx * s + offy * c;
            float u = 2.0f * ox / w, vv = 2.0f * oy / h;
            float cent = fmaxf(1.0f - sqrtf((u * u + vv * vv + 1e-8f) * 0.5f), 0.0f);
            float iou = riou_pair(bcx1, bcy1, bw1, bh1, bc1, bs1, ar1,
                                  bcx, bcy, w, h, c, s, a2);
            float prob = expf(probs[i * 15 + sl[g]] - pm) / psum;
            cost = 0.2f * cent + 0.2f * iou + 0.6f * prob;
        }
        unsigned bal = __ballot_sync(0xFFFFFFFFu, v);
        if (bal) {
            int leader = __ffs(bal) - 1;
            int base;
            if (lane == leader) base = atomicAdd(&g_cnt[g], __popc(bal));
            base = __shfl_sync(0xFFFFFFFFu, base, leader);
            if (v) {
                int pos = base + __popc(bal & ((1u << lane) - 1u));
                if (pos < LCAP) {
                    g_lv[g * LCAP + pos] = cost;
                    g_li[g * LCAP + pos] = i;
                }
            }
        }
    }
}

// ---------------------------------------------------------------------------
// Kernel 2: each block redundantly computes top-k/counts/override from the
// compacted lists, then writes outputs for its 1024-point slice.
// Last-arriving block resets persistent scratch for the next replay.
// ---------------------------------------------------------------------------
__global__ void __launch_bounds__(1024)
kCF(const float* __restrict__ pts, const float* __restrict__ stride,
    const float* __restrict__ gtb, const int* __restrict__ glab,
    float* __restrict__ out, int N, int G)
{
    __shared__ float sg[GMX * 8];
    __shared__ int sl[GMX];
    __shared__ int scnt[GMX];
    __shared__ unsigned long long sAK[GMX];
    __shared__ int2 ssel[512];
    __shared__ int sSelCnt;
    __shared__ int sCounts[GMX];
    __shared__ unsigned sbits[1024];
    __shared__ int sOvr[1024];

    int tid = threadIdx.x;
    if (tid < GMX) {
        if (tid < G) {
            float cx = gtb[tid * 5 + 0], cy = gtb[tid * 5 + 1];
            float w = gtb[tid * 5 + 2], h = gtb[tid * 5 + 3], a = gtb[tid * 5 + 4];
            sg[tid * 8 + 0] = cx; sg[tid * 8 + 1] = cy;
            sg[tid * 8 + 2] = w;  sg[tid * 8 + 3] = h;
            sg[tid * 8 + 4] = cosf(a); sg[tid * 8 + 5] = sinf(a);
            sg[tid * 8 + 6] = a; sg[tid * 8 + 7] = w * h;
            sl[tid] = glab[tid];
            int n = g_cnt[tid];
            scnt[tid] = (n > LCAP) ? LCAP : n;
            sAK[tid] = g_anchorKey[tid];
        } else {
            scnt[tid] = 0; sAK[tid] = 0ULL;
        }
        sCounts[tid] = 0;
    }
    if (tid == 0) sSelCnt = 0;
    sbits[tid] = 0u;
    sOvr[tid] = -1;
    __syncthreads();

    // scratch reset by last-arriving block (wait-free)
    if (tid == 0) {
        int a = atomicAdd(&g_ack, 1);
        if (a == (int)gridDim.x - 1) {
            for (int q = 0; q < GMX; ++q) { g_cnt[q] = 0; g_anchorKey[q] = 0ULL; }
            g_ack = 0;
            __threadfence();
        }
    }

    // top-15 per gt: warp w handles gt w
    int g = tid >> 5;
    int lane = tid & 31;
    if (g < G) {
        int n = scnt[g];
        unsigned long long used = 0ULL;
        for (int it = 0; it < TOPK_K; ++it) {
            float bv = -1.0f; int bi = 0x7fffffff; int bk = -1;
            for (int k = 0; k * 32 + lane < n; ++k) {
                if ((used >> k) & 1ULL) continue;
                int e = k * 32 + lane;
                float v = g_lv[g * LCAP + e];
                int id = g_li[g * LCAP + e];
                if (v > bv || (v == bv && id < bi)) { bv = v; bi = id; bk = k; }
            }
            unsigned long long myKey = (bk >= 0)
                ? (((unsigned long long)__float_as_uint(bv) << 32) | (unsigned)(~(unsigned)bi))
                : 0ULL;
            unsigned long long key = myKey;
#pragma unroll
            for (int off = 16; off > 0; off >>= 1) {
                unsigned long long o = __shfl_down_sync(0xFFFFFFFFu, key, off);
                if (o > key) key = o;
            }
            key = __shfl_sync(0xFFFFFFFFu, key, 0);
            if (key == 0ULL) break;
            if (myKey == key) {
                used |= 1ULL << bk;
                int pos = atomicAdd(&sSelCnt, 1);
                ssel[pos] = make_int2(bi, g);
            }
        }
    }
    __syncthreads();

    int sc = sSelCnt;

    // counts: per selected (i,og), owner = lowest set bit of union-bits(i)
    if (tid < sc) {
        int i = ssel[tid].x, og = ssel[tid].y;
        unsigned bits = 0u;
        for (int u = 0; u < sc; ++u)
            if (ssel[u].x == i) bits |= 1u << ssel[u].y;
        if ((bits & (0u - bits)) == (1u << og)) {
            float best = 0.0f; int gi = 0;
            for (int q = 0; q < G; ++q) {
                if ((bits >> q) & 1u) {
                    float area = sg[q * 8 + 7];
                    if (area > best) { best = area; gi = q; }
                }
            }
            atomicAdd(&sCounts[gi], 1);
        }
    }

    // slice bits
    int lo = blockIdx.x * 1024;
    for (int t = tid; t < sc; t += 1024) {
        int i = ssel[t].x;
        if (i >= lo && i < lo + 1024) atomicOr(&sbits[i - lo], 1u << ssel[t].y);
    }
    __syncthreads();

    // override (serial ascending g => last wins)
    if (tid == 0) {
        for (int q = 0; q < G; ++q) {
            if (sCounts[q] == 0) {
                unsigned long long k = sAK[q];
                int ai = (int)(~(unsigned)(k & 0xFFFFFFFFULL));
                if (ai >= lo && ai < lo + 1024 && ai < N) sOvr[ai - lo] = q;
            }
        }
    }
    __syncthreads();

    // outputs for this slice
    int i = lo + tid;
    if (i >= N) return;
    unsigned bits = sbits[tid];
    float best = 0.0f; int gi = 0;
    while (bits) {
        int q = __ffs(bits) - 1;
        bits &= bits - 1u;
        float area = sg[q * 8 + 7];
        if (area > best) { best = area; gi = q; }
    }
    int label = (best == 0.0f) ? BG_LAB : sl[gi];
    int ov = sOvr[tid];
    if (ov >= 0) { gi = ov; label = sl[ov]; }

    float cx = sg[gi * 8 + 0], cy = sg[gi * 8 + 1];
    float w = sg[gi * 8 + 2], h = sg[gi * 8 + 3];
    float c = sg[gi * 8 + 4], s = sg[gi * 8 + 5];
    float ang = sg[gi * 8 + 6];
    float offx = pts[i * 2 + 0] - cx, offy = pts[i * 2 + 1] - cy;
    float ox = offx * c + offy * s;
    float oy = -offx * s + offy * c;
    float st = stride[i];

    out[i] = (float)label;
    out[N + i * 4 + 0] = (w * 0.5f + ox) / st;
    out[N + i * 4 + 1] = (h * 0.5f + oy) / st;
    out[N + i * 4 + 2] = (w * 0.5f - ox) / st;
    out[N + i * 4 + 3] = (h * 0.5f - oy) / st;
    out[N * 5 + i] = ang;
}

// ---------------------------------------------------------------------------
extern "C" void kernel_launch(void* const* d_in, const int* in_sizes, int n_in,
                              void* d_out, int out_size)
{
    const float* points = (const float*)d_in[0];
    const float* rr     = (const float*)d_in[1];
    const float* stride = (const float*)d_in[2];
    const float* gtb    = (const float*)d_in[3];
    const int*   glab   = (const int*)d_in[4];
    const float* preds  = (const float*)d_in[5];
    const float* probs  = (const float*)d_in[6];
    float* out = (float*)d_out;

    int N = in_sizes[0] / 2;
    int G = in_sizes[3] / 5;
    if (G > GMX) G = GMX;
    if (N > NMAX) N = NMAX;

    kMain<<<(N + 255) / 256, 256>>>(points, rr, stride, gtb, glab, preds, probs, N, G);
    kCF<<<(N + 1023) / 1024, 1024>>>(points, stride, gtb, glab, out, N, G);
}

// round 5
// speedup vs baseline: 1.0920x; 1.0920x over previous
#include <cuda_runtime.h>
#include <math.h>

#define GMX 32
#define LCAP 2048
#define TOPK_K 15
#define BG_LAB 15
#define PI_F   3.14159265358979323846f
#define HPI_F  1.57079632679489661923f

// -------- persistent device scratch (zero-init; re-zeroed each run) --------
__device__ int g_cnt[GMX];
__device__ unsigned long long g_anchorKey[GMX];
__device__ int g_bar1;
__device__ int g_bar2;
__device__ float g_lv[GMX * LCAP];
__device__ int   g_li[GMX * LCAP];

// ---------------------------------------------------------------------------
// Rotated IoU (reference-faithful polygon construction)
// ---------------------------------------------------------------------------
__device__ __forceinline__ void make_corners(float cx, float cy, float w, float h,
                                             float c, float s, float* X, float* Y)
{
    float w2 = w * 0.5f, h2 = h * 0.5f;
    X[0] = cx + (w2 * c + h2 * s);  Y[0] = cy + (w2 * s - h2 * c);
    X[1] = cx + (w2 * c - h2 * s);  Y[1] = cy + (w2 * s + h2 * c);
    X[2] = cx + (-w2 * c - h2 * s); Y[2] = cy + (-w2 * s + h2 * c);
    X[3] = cx + (-w2 * c + h2 * s); Y[3] = cy + (-w2 * s - h2 * c);
}

__device__ float riou_pair(float b1cx, float b1cy, float b1w, float b1h,
                           float b1c, float b1s, float a1,
                           float b2cx, float b2cy, float b2w, float b2h,
                           float b2c, float b2s, float a2)
{
    {
        float ddx = b1cx - b2cx, ddy = b1cy - b2cy;
        float r1 = 0.5f * sqrtf(b1w * b1w + b1h * b1h);
        float r2 = 0.5f * sqrtf(b2w * b2w + b2h * b2h);
        float rrs = r1 + r2 + 0.5f;
        if (ddx * ddx + ddy * ddy > rrs * rrs) return 0.0f;
    }

    float c1x[4], c1y[4], c2x[4], c2y[4];
    make_corners(b1cx, b1cy, b1w, b1h, b1c, b1s, c1x, c1y);
    make_corners(b2cx, b2cy, b2w, b2h, b2c, b2s, c2x, c2y);

    float X[24], Y[24], A[24];
    int cnt = 0;
    float sx = 0.0f, sy = 0.0f;

#pragma unroll
    for (int a = 0; a < 4; a++) {
        float px = c1x[a], py = c1y[a];
        float d1x = c1x[(a + 1) & 3] - px, d1y = c1y[(a + 1) & 3] - py;
#pragma unroll
        for (int b = 0; b < 4; b++) {
            float qx = c2x[b], qy = c2y[b];
            float d2x = c2x[(b + 1) & 3] - qx, d2y = c2y[(b + 1) & 3] - qy;
            float den = d1x * d2y - d1y * d2x;
            bool dok = fabsf(den) > 1e-10f;
            float safe = dok ? den : 1.0f;
            float qpx = qx - px, qpy = qy - py;
            float t = (qpx * d2y - qpy * d2x) / safe;
            float u = (qpx * d1y - qpy * d1x) / safe;
            if (dok && t >= 0.0f && t <= 1.0f && u >= 0.0f && u <= 1.0f) {
                float ix = px + t * d1x, iy = py + t * d1y;
                X[cnt] = ix; Y[cnt] = iy; cnt++;
                sx += ix; sy += iy;
            }
        }
    }
#pragma unroll
    for (int a = 0; a < 4; a++) {
        float rx = c1x[a] - b2cx, ry = c1y[a] - b2cy;
        float xx = rx * b2c + ry * b2s;
        float yy = -rx * b2s + ry * b2c;
        if (fabsf(xx) <= b2w * 0.5f + 1e-6f && fabsf(yy) <= b2h * 0.5f + 1e-6f) {
            X[cnt] = c1x[a]; Y[cnt] = c1y[a]; cnt++;
            sx += c1x[a]; sy += c1y[a];
        }
    }
#pragma unroll
    for (int b = 0; b < 4; b++) {
        float rx = c2x[b] - b1cx, ry = c2y[b] - b1cy;
        float xx = rx * b1c + ry * b1s;
        float yy = -rx * b1s + ry * b1c;
        if (fabsf(xx) <= b1w * 0.5f + 1e-6f && fabsf(yy) <= b1h * 0.5f + 1e-6f) {
            X[cnt] = c2x[b]; Y[cnt] = c2y[b]; cnt++;
            sx += c2x[b]; sy += c2y[b];
        }
    }

    if (cnt == 0) return 0.0f;
    float ctrx = sx / (float)cnt, ctry = sy / (float)cnt;

    for (int j = 0; j < cnt; j++) A[j] = atan2f(Y[j] - ctry, X[j] - ctrx);
    for (int j = 1; j < cnt; j++) {
        float aj = A[j], xj = X[j], yj = Y[j];
        int k = j - 1;
        while (k >= 0 && A[k] > aj) {
            A[k + 1] = A[k]; X[k + 1] = X[k]; Y[k + 1] = Y[k]; k--;
        }
        A[k + 1] = aj; X[k + 1] = xj; Y[k + 1] = yj;
    }
    float acc = 0.0f;
    for (int j = 0; j < cnt; j++) {
        int k = (j + 1 < cnt) ? j + 1 : 0;
        float vax = X[j] - ctrx, vay = Y[j] - ctry;
        float vbx = X[k] - ctrx, vby = Y[k] - ctry;
        acc += vax * vby - vay * vbx;
    }
    float inter = 0.5f * fabsf(acc);
    return inter / fmaxf(a1 + a2 - inter, 1e-8f);
}

// ---------------------------------------------------------------------------
// Single fused kernel: phase 1 (gating/cost/compaction/anchor) -> global
// barrier -> phase 2 (rank-based top-k, counts, override, outputs).
// Co-residency guaranteed: ceil(N/256)=86 blocks <= 148 SMs, 256 thr/block.
// ---------------------------------------------------------------------------
__global__ void __launch_bounds__(256)
kAll(const float* __restrict__ pts, const float* __restrict__ rr,
     const float* __restrict__ stride, const float* __restrict__ gtb,
     const int* __restrict__ glab, const float* __restrict__ preds,
     const float* __restrict__ probs, float* __restrict__ out, int N, int G)
{
    __shared__ float sg[GMX * 8];   // cx,cy,w,h,cos,sin,angle,area
    __shared__ int sl[GMX];
    __shared__ unsigned long long sA[GMX];
    __shared__ int scnt[GMX];
    __shared__ unsigned long long sAK[GMX];
    __shared__ int2 ssel[512];
    __shared__ int sSelCnt;
    __shared__ int sCounts[GMX];
    __shared__ unsigned sbits[256];
    __shared__ int sOvr[256];

    int tid = threadIdx.x;
    int lane = tid & 31;
    if (tid < GMX) {
        sA[tid] = 0ULL;
        if (tid < G) {
            float cx = gtb[tid * 5 + 0], cy = gtb[tid * 5 + 1];
            float w = gtb[tid * 5 + 2], h = gtb[tid * 5 + 3], a = gtb[tid * 5 + 4];
            sg[tid * 8 + 0] = cx; sg[tid * 8 + 1] = cy;
            sg[tid * 8 + 2] = w;  sg[tid * 8 + 3] = h;
            sg[tid * 8 + 4] = cosf(a); sg[tid * 8 + 5] = sinf(a);
            sg[tid * 8 + 6] = a; sg[tid * 8 + 7] = w * h;
            sl[tid] = glab[tid];
        }
    }
    __syncthreads();

    // ===================== PHASE 1: per-point =====================
    int i = blockIdx.x * 256 + tid;
    bool inb = (i < N);

    float px = 0.f, py = 0.f, st = 1.f, r0 = 0.f, r1 = 0.f;
    if (inb) {
        px = pts[i * 2 + 0]; py = pts[i * 2 + 1];
        st = stride[i];
        r0 = rr[i * 2 + 0]; r1 = rr[i * 2 + 1];
    }
    float crad = 1.5f * st;

    unsigned mask = 0u;
    for (int g = 0; g < G; ++g) {
        float bcx = sg[g * 8 + 0], bcy = sg[g * 8 + 1];
        float w = sg[g * 8 + 2], h = sg[g * 8 + 3];
        float c = sg[g * 8 + 4], s = sg[g * 8 + 5];
        float offx = px - bcx, offy = py - bcy;
        float ox = offx * c + offy * s;
        float oy = -offx * s + offy * c;
        float t0 = w * 0.5f + ox, t1 = h * 0.5f + oy;
        float t2 = w * 0.5f - ox, t3 = h * 0.5f - oy;
        float mn = fminf(fminf(t0, t1), fminf(t2, t3));
        float mx = fmaxf(fmaxf(t0, t1), fmaxf(t2, t3));
        float u = 2.0f * ox / w, v = 2.0f * oy / h;
        float cent = fmaxf(1.0f - sqrtf((u * u + v * v + 1e-8f) * 0.5f), 0.0f);
        bool valid = inb && (mn > 0.0f) && (fabsf(ox) < crad) && (fabsf(oy) < crad)
                     && (mx >= r0) && (mx <= r1);
        if (valid) mask |= 1u << g;

        if (inb) {
            unsigned long long key =
                ((unsigned long long)__float_as_uint(cent) << 32) | (unsigned)(~(unsigned)i);
            // hint-read: only atomic when improving (rare)
            if (key > *((volatile unsigned long long*)&sA[g]))
                atomicMax(&sA[g], key);
        }
    }
    __syncthreads();
    if (tid < G) {
        unsigned long long v = sA[tid];
        if (v != 0ULL) atomicMax(&g_anchorKey[tid], v);
    }

    // warp-union of valid gts
    unsigned wm = mask;
#pragma unroll
    for (int off = 16; off > 0; off >>= 1) wm |= __shfl_xor_sync(0xFFFFFFFFu, wm, off);

    if (wm) {
        // lazy per-point decode + softmax prep (only threads with a valid gt)
        float bcx1 = 0.f, bcy1 = 0.f, bw1 = 0.f, bh1 = 0.f, bc1 = 1.f, bs1 = 0.f, ar1 = 0.f;
        float pm = 0.f, psum = 1.f;
        if (mask) {
            float d0 = preds[i * 5 + 0] * st, d1 = preds[i * 5 + 1] * st;
            float d2 = preds[i * 5 + 2] * st, d3 = preds[i * 5 + 3] * st;
            float ang = preds[i * 5 + 4];
            float c = cosf(ang), s = sinf(ang);
            bw1 = d0 + d2; bh1 = d1 + d3;
            float otx = (d2 - d0) * 0.5f, oty = (d3 - d1) * 0.5f;
            bcx1 = px + (c * otx - s * oty);
            bcy1 = py + (s * otx + c * oty);
            float x = ang + HPI_F;
            float r = fmodf(x, PI_F);
            if (r < 0.0f) r += PI_F;
            float a = r - HPI_F;
            bc1 = cosf(a); bs1 = sinf(a);
            ar1 = bw1 * bh1;

            pm = -1e30f;
#pragma unroll
            for (int k = 0; k < 15; k++) pm = fmaxf(pm, probs[i * 15 + k]);
            psum = 0.0f;
#pragma unroll
            for (int k = 0; k < 15; k++) psum += expf(probs[i * 15 + k] - pm);
        }

        unsigned wml = wm;
        while (wml) {
            int g = __ffs(wml) - 1;
            wml &= wml - 1u;
            bool v = (mask >> g) & 1u;
            float cost = 0.0f;
            if (v) {
                float bcx = sg[g * 8 + 0], bcy = sg[g * 8 + 1];
                float w = sg[g * 8 + 2], h = sg[g * 8 + 3];
                float c = sg[g * 8 + 4], s = sg[g * 8 + 5];
                float a2 = sg[g * 8 + 7];
                float offx = px - bcx, offy = py - bcy;
                float ox = offx * c + offy * s;
                float oy = -offx * s + offy * c;
                float u = 2.0f * ox / w, vv = 2.0f * oy / h;
                float cent = fmaxf(1.0f - sqrtf((u * u + vv * vv + 1e-8f) * 0.5f), 0.0f);
                float iou = riou_pair(bcx1, bcy1, bw1, bh1, bc1, bs1, ar1,
                                      bcx, bcy, w, h, c, s, a2);
                float prob = expf(probs[i * 15 + sl[g]] - pm) / psum;
                cost = 0.2f * cent + 0.2f * iou + 0.6f * prob;
            }
            unsigned bal = __ballot_sync(0xFFFFFFFFu, v);
            if (bal) {
                int leader = __ffs(bal) - 1;
                int base;
                if (lane == leader) base = atomicAdd(&g_cnt[g], __popc(bal));
                base = __shfl_sync(0xFFFFFFFFu, base, leader);
                if (v) {
                    int pos = base + __popc(bal & ((1u << lane) - 1u));
                    if (pos < LCAP) {
                        g_lv[g * LCAP + pos] = cost;
                        g_li[g * LCAP + pos] = i;
                    }
                }
            }
        }
    }

    // ===================== GLOBAL BARRIER =====================
    __threadfence();
    __syncthreads();
    if (tid == 0) {
        atomicAdd(&g_bar1, 1);
        while (*((volatile int*)&g_bar1) < (int)gridDim.x) __nanosleep(64);
    }
    __syncthreads();
    __threadfence();

    // ===================== PHASE 2 =====================
    if (tid < GMX) {
        if (tid < G) {
            int n = g_cnt[tid];
            scnt[tid] = (n > LCAP) ? LCAP : n;
            sAK[tid] = g_anchorKey[tid];
        } else { scnt[tid] = 0; sAK[tid] = 0ULL; }
        sCounts[tid] = 0;
    }
    if (tid == 0) sSelCnt = 0;
    sbits[tid] = 0u;
    sOvr[tid] = -1;
    __syncthreads();

    // rank-based top-15: entry selected iff < 15 entries lexicographically above
    {
        int wid = tid >> 5;
        for (int g = wid; g < G; g += 8) {
            int n = scnt[g];
            for (int e = lane; e < n; e += 32) {
                float v = g_lv[g * LCAP + e];
                int id = g_li[g * LCAP + e];
                int rank = 0;
                for (int e2 = 0; e2 < n; ++e2) {
                    float v2 = g_lv[g * LCAP + e2];
                    int id2 = g_li[g * LCAP + e2];
                    rank += (v2 > v) || (v2 == v && id2 < id);
                }
                if (rank < TOPK_K) {
                    int pos = atomicAdd(&sSelCnt, 1);
                    ssel[pos] = make_int2(id, g);
                }
            }
        }
    }
    __syncthreads();

    int sc = sSelCnt;

    // counts: per selected (i,og), owner = lowest set bit of union-bits(i)
    for (int t = tid; t < sc; t += 256) {
        int pi = ssel[t].x, og = ssel[t].y;
        unsigned bits = 0u;
        for (int u = 0; u < sc; ++u)
            if (ssel[u].x == pi) bits |= 1u << ssel[u].y;
        if ((bits & (0u - bits)) == (1u << og)) {
            float best = 0.0f; int gi = 0;
            for (int q = 0; q < G; ++q) {
                if ((bits >> q) & 1u) {
                    float area = sg[q * 8 + 7];
                    if (area > best) { best = area; gi = q; }
                }
            }
            atomicAdd(&sCounts[gi], 1);
        }
    }

    // slice bits for this block's 256 points
    int lo = blockIdx.x * 256;
    for (int t = tid; t < sc; t += 256) {
        int pi = ssel[t].x;
        if (pi >= lo && pi < lo + 256) atomicOr(&sbits[pi - lo], 1u << ssel[t].y);
    }
    __syncthreads();

    // override (serial ascending g => last wins), restricted to this slice
    if (tid == 0) {
        for (int q = 0; q < G; ++q) {
            if (sCounts[q] == 0) {
                unsigned long long k = sAK[q];
                int ai = (int)(~(unsigned)(k & 0xFFFFFFFFULL));
                if (ai >= lo && ai < lo + 256 && ai < N) sOvr[ai - lo] = q;
            }
        }
    }
    __syncthreads();

    // outputs for this slice
    if (inb) {
        unsigned bits = sbits[tid];
        float best = 0.0f; int gi = 0;
        while (bits) {
            int q = __ffs(bits) - 1;
            bits &= bits - 1u;
            float area = sg[q * 8 + 7];
            if (area > best) { best = area; gi = q; }
        }
        int label = (best == 0.0f) ? BG_LAB : sl[gi];
        int ov = sOvr[tid];
        if (ov >= 0) { gi = ov; label = sl[ov]; }

        float cx = sg[gi * 8 + 0], cy = sg[gi * 8 + 1];
        float w = sg[gi * 8 + 2], h = sg[gi * 8 + 3];
        float c = sg[gi * 8 + 4], s = sg[gi * 8 + 5];
        float ang = sg[gi * 8 + 6];
        float offx = px - cx, offy = py - cy;
        float ox = offx * c + offy * s;
        float oy = -offx * s + offy * c;

        out[i] = (float)label;
        out[N + i * 4 + 0] = (w * 0.5f + ox) / st;
        out[N + i * 4 + 1] = (h * 0.5f + oy) / st;
        out[N + i * 4 + 2] = (w * 0.5f - ox) / st;
        out[N + i * 4 + 3] = (h * 0.5f - oy) / st;
        out[N * 5 + i] = ang;
    }

    // final reset by last-finishing block (safe: all blocks passed the spin)
    __syncthreads();
    if (tid == 0) {
        __threadfence();
        int a = atomicAdd(&g_bar2, 1);
        if (a == (int)gridDim.x - 1) {
            for (int q = 0; q < GMX; ++q) { g_cnt[q] = 0; g_anchorKey[q] = 0ULL; }
            g_bar1 = 0;
            g_bar2 = 0;
            __threadfence();
        }
    }
}

// ---------------------------------------------------------------------------
extern "C" void kernel_launch(void* const* d_in, const int* in_sizes, int n_in,
                              void* d_out, int out_size)
{
    const float* points = (const float*)d_in[0];
    const float* rr     = (const float*)d_in[1];
    const float* stride = (const float*)d_in[2];
    const float* gtb    = (const float*)d_in[3];
    const int*   glab   = (const int*)d_in[4];
    const float* preds  = (const float*)d_in[5];
    const float* probs  = (const float*)d_in[6];
    float* out = (float*)d_out;

    int N = in_sizes[0] / 2;
    int G = in_sizes[3] / 5;
    if (G > GMX) G = GMX;

    kAll<<<(N + 255) / 256, 256>>>(points, rr, stride, gtb, glab, preds, probs, out, N, G);
}